// round 16
// baseline (speedup 1.0000x reference)
#include <cuda_runtime.h>
#include <cuda_bf16.h>
#include <cuda_fp16.h>
#include <stdint.h>
#include <math.h>

// Problem constants: b=4, n=4096 -> T=16384 tokens, dim=1024, heads=16, d=64
#define TOKENS 16384
#define DIM    1024
#define QKVDIM 3072
#define NHEAD  16
#define HDIM   64
#define SEQ    4096

// GEMM tiling (K is always 1024)
#define BM 128
#define BN 128
#define BK 64
#define KCHUNKS (DIM / BK)          // 16
#define STAGES 3
#define ARR_BYTES (BM * BK * 2)     // 16384 per operand array per stage
#define STAGE_BYTES (2 * ARR_BYTES) // 32768 (A, B)
#define GEMM_SMEM (STAGES * STAGE_BYTES)        // 98304
#define GEMM_SMEM_TOTAL (GEMM_SMEM + 64)        // + mbarriers

// ---------------------------------------------------------------------------
// Scratch (device globals; kernel_launch is allocation-free)
// ---------------------------------------------------------------------------
__device__ __align__(256) __half g_xh  [(size_t)TOKENS * DIM];
__device__ __align__(256) __half g_wqh [(size_t)QKVDIM * DIM]; // [N,K]
__device__ __align__(256) __half g_wph [(size_t)DIM * DIM];    // [N,K]
__device__ __align__(256) __half g_ah  [(size_t)TOKENS * DIM];
__device__ __align__(256) __half g_qkv [(size_t)TOKENS * QKVDIM];  // fp16

// ---------------------------------------------------------------------------
// PTX helpers (baseline sm_80+ features only — tcgen05 unavailable on target)
// ---------------------------------------------------------------------------
__device__ __forceinline__ uint32_t s2u(const void* p) {
    uint32_t a;
    asm("{ .reg .u64 t; cvta.to.shared.u64 t, %1; cvt.u32.u64 %0, t; }"
        : "=r"(a) : "l"(p));
    return a;
}

__device__ __forceinline__ void cp_async16(uint32_t dst, const void* gsrc) {
    asm volatile("cp.async.cg.shared.global [%0], [%1], 16;"
                 :: "r"(dst), "l"(__cvta_generic_to_global(gsrc)) : "memory");
}

// async-arrive: when THIS thread's prior cp.asyncs complete, arrive on mbar
// (.noinc: consumes one of the preset arrival count)
__device__ __forceinline__ void cp_async_mbar_arrive(uint32_t mbar) {
    asm volatile("cp.async.mbarrier.arrive.noinc.shared::cta.b64 [%0];"
                 :: "r"(mbar) : "memory");
}

#define MBAR_INIT(addr, cnt) \
    asm volatile("mbarrier.init.shared.b64 [%0], %1;" :: "r"(addr), "r"(cnt) : "memory")

#define MBAR_ARRIVE(addr) \
    asm volatile("mbarrier.arrive.shared.b64 _, [%0];" :: "r"(addr) : "memory")

#define MBAR_WAIT(addr, ph) do { \
    uint32_t _m = (addr); uint32_t _p = (ph); uint32_t _d; \
    asm volatile("{\n\t.reg .pred p;\n\t" \
        "mbarrier.try_wait.parity.acquire.cta.shared::cta.b64 p, [%1], %2;\n\t" \
        "selp.b32 %0, 1, 0, p;\n\t}" : "=r"(_d) : "r"(_m), "r"(_p) : "memory"); \
    if (!_d) { \
        asm volatile("{\n\t.reg .pred P1;\n\t" \
            "WL_%=:\n\t" \
            "mbarrier.try_wait.parity.acquire.cta.shared::cta.b64 P1, [%0], %1, 0x989680;\n\t" \
            "@P1 bra.uni WD_%=;\n\t" \
            "bra.uni WL_%=;\n\t" \
            "WD_%=:\n\t}" :: "r"(_m), "r"(_p) : "memory"); \
    } \
} while (0)

#define FENCE_ASYNC_SHARED() asm volatile("fence.proxy.async.shared::cta;" ::: "memory")

__device__ __forceinline__ void ldsm_x4(uint32_t& r0, uint32_t& r1,
                                        uint32_t& r2, uint32_t& r3, uint32_t addr) {
    asm volatile("ldmatrix.sync.aligned.m8n8.x4.shared.b16 {%0,%1,%2,%3}, [%4];"
                 : "=r"(r0), "=r"(r1), "=r"(r2), "=r"(r3) : "r"(addr));
}
__device__ __forceinline__ void ldsm_x4_t(uint32_t& r0, uint32_t& r1,
                                          uint32_t& r2, uint32_t& r3, uint32_t addr) {
    asm volatile("ldmatrix.sync.aligned.m8n8.x4.trans.shared.b16 {%0,%1,%2,%3}, [%4];"
                 : "=r"(r0), "=r"(r1), "=r"(r2), "=r"(r3) : "r"(addr));
}

__device__ __forceinline__ void mma16816(float* c, const uint32_t* a, const uint32_t* b) {
    asm volatile(
        "mma.sync.aligned.m16n8k16.row.col.f32.f16.f16.f32 "
        "{%0,%1,%2,%3}, {%4,%5,%6,%7}, {%8,%9}, {%0,%1,%2,%3};"
        : "+f"(c[0]), "+f"(c[1]), "+f"(c[2]), "+f"(c[3])
        : "r"(a[0]), "r"(a[1]), "r"(a[2]), "r"(a[3]), "r"(b[0]), "r"(b[1]));
}

// Swizzled smem byte offset for a (row, 16B-unit) within a [rows][64] f16 tile.
__device__ __forceinline__ uint32_t sw_off(int row, int u) {
    return (uint32_t)(row * 128 + (((u ^ (row & 7)) & 7) << 4));
}

// ---------------------------------------------------------------------------
// GEMM: C[M,N] = A @ B^T, fp16 operands, fp32 accumulate.
// OUTHALF selects fp16 or fp32(+bias) output.
// grid (N/128, M/128), 256 threads (8 warps, each 64x32). 2 CTAs/SM.
// Decoupled mbarrier pipeline: per-stage full (count=256, async-arrive) and
// empty (count=8, one arrive/warp) barriers; NO per-chunk __syncthreads.
// ---------------------------------------------------------------------------
template <bool BIAS, bool OUTHALF>
__global__ __launch_bounds__(256, 2)
void mma_gemm(const __half* __restrict__ A, const __half* __restrict__ B,
              const float* __restrict__ bias, void* __restrict__ Cout, int N) {
    extern __shared__ __align__(256) char smem[];
    const uint32_t sb = s2u(smem);
    const int tid = threadIdx.x;
    const int wid = tid >> 5, lane = tid & 31;
    const int m0 = blockIdx.y * BM;
    const int n0 = blockIdx.x * BN;

    const uint32_t bar_full  = sb + GEMM_SMEM;       // 3 x 8B
    const uint32_t bar_empty = sb + GEMM_SMEM + 24;  // 3 x 8B

    if (tid == 0) {
#pragma unroll
        for (int s = 0; s < STAGES; s++) {
            MBAR_INIT(bar_full + s * 8, 256);
            MBAR_INIT(bar_empty + s * 8, 8);
        }
        FENCE_ASYNC_SHARED();
    }
    __syncthreads();   // only block-wide barrier: after init

    const __half* bases[2] = { A + (size_t)m0 * DIM, B + (size_t)n0 * DIM };

    // --- async stage loader: 2048 x 16B units per stage, 8 per thread ---
    auto load_stage = [&](int s, int c) {
#pragma unroll
        for (int i = 0; i < 8; i++) {
            int u = tid + i * 256;
            int arr = u >> 10;           // 0..1
            int idx = u & 1023;
            int row = idx >> 3;          // 0..127
            int cu  = idx & 7;           // 16B unit within 128B row
            const char* src = (const char*)bases[arr]
                              + (size_t)row * (DIM * 2) + c * (BK * 2) + cu * 16;
            uint32_t dst = sb + s * STAGE_BYTES + arr * ARR_BYTES + sw_off(row, cu);
            cp_async16(dst, src);
        }
        cp_async_mbar_arrive(bar_full + s * 8);
    };

    // prologue: fill stages 0,1 (no empty-wait needed: never consumed yet)
    load_stage(0, 0);
    load_stage(1, 1);

    const int wr = wid >> 2, wc = wid & 3;   // 2x4 warp grid
    const int wo = wr * 64, no = wc * 32;

    float acc[4][4][4];
#pragma unroll
    for (int mi = 0; mi < 4; mi++)
#pragma unroll
        for (int ni = 0; ni < 4; ni++)
#pragma unroll
            for (int e = 0; e < 4; e++) acc[mi][ni][e] = 0.f;

    const int la = lane & 15;

    for (int c = 0; c < KCHUNKS; c++) {
        const int s = c % STAGES;
        // consumer: wait fill #(c/3) of stage s
        MBAR_WAIT(bar_full + s * 8, (uint32_t)((c / STAGES) & 1));

        // producer: refill stage for chunk c+2 (waits consumption of c-1)
        const int cn = c + 2;
        if (cn < KCHUNKS) {
            const int s2 = cn % STAGES;
            const int k2 = cn / STAGES;
            MBAR_WAIT(bar_empty + s2 * 8, (uint32_t)((k2 & 1) ^ 1));
            load_stage(s2, cn);
        }

        const uint32_t st = sb + s * STAGE_BYTES;
        const uint32_t sA = st;
        const uint32_t sB = st + ARR_BYTES;

#pragma unroll
        for (int k16 = 0; k16 < 4; k16++) {
            // B fragments for all 4 ni via x4 ldmatrix pairs.
            uint32_t bh[4][2];
            const int brow_lo = (lane >> 4) & 1;         // which ni within pair
            const int bu = k16 * 2 + ((lane >> 3) & 1);  // k-unit
#pragma unroll
            for (int p = 0; p < 2; p++) {
                const int row = no + (p * 2 + brow_lo) * 8 + (lane & 7);
                uint32_t off = sw_off(row, bu);
                ldsm_x4(bh[p*2][0], bh[p*2][1], bh[p*2+1][0], bh[p*2+1][1], sB + off);
            }
            const int au = k16 * 2 + (lane >> 4);
#pragma unroll
            for (int mi = 0; mi < 4; mi++) {
                uint32_t ah[4];
                const int row = wo + mi * 16 + la;
                uint32_t off = sw_off(row, au);
                ldsm_x4(ah[0], ah[1], ah[2], ah[3], sA + off);
#pragma unroll
                for (int ni = 0; ni < 4; ni++) mma16816(acc[mi][ni], ah, bh[ni]);
            }
        }
        // this warp done with stage s
        if (lane == 0) MBAR_ARRIVE(bar_empty + s * 8);
    }

    // epilogue (no trailing barrier needed: per-warp output is independent)
    const int tg = lane >> 2, tq = lane & 3;
#pragma unroll
    for (int mi = 0; mi < 4; mi++) {
#pragma unroll
        for (int ni = 0; ni < 4; ni++) {
            const float* cc = acc[mi][ni];
            int col = n0 + no + ni * 8 + tq * 2;
            size_t r0 = (size_t)(m0 + wo + mi * 16 + tg);
            if (OUTHALF) {
                __half* C = (__half*)Cout;
                *(__half2*)(C + r0 * N + col) = __floats2half2_rn(cc[0], cc[1]);
                *(__half2*)(C + (r0 + 8) * N + col) = __floats2half2_rn(cc[2], cc[3]);
            } else {
                float* C = (float*)Cout;
                float bx = 0.f, by = 0.f;
                if (BIAS) { bx = bias[col]; by = bias[col + 1]; }
                float2 v0 = {cc[0] + bx, cc[1] + by};
                float2 v1 = {cc[2] + bx, cc[3] + by};
                *(float2*)(C + r0 * N + col) = v0;
                *(float2*)(C + (r0 + 8) * N + col) = v1;
            }
        }
    }
}

// ---------------------------------------------------------------------------
// Conversions
// ---------------------------------------------------------------------------
__global__ void convert_A_kernel(const float* __restrict__ X,
                                 __half* __restrict__ H, size_t total8) {
    size_t t = (size_t)blockIdx.x * blockDim.x + threadIdx.x;
    if (t >= total8) return;
    const float* src = X + t * 8;
    float4 f0 = *(const float4*)src;
    float4 f1 = *(const float4*)(src + 4);
    float v[8] = {f0.x, f0.y, f0.z, f0.w, f1.x, f1.y, f1.z, f1.w};
    union { __half b[8]; uint4 q; } Hh;
#pragma unroll
    for (int i = 0; i < 8; i++) Hh.b[i] = __float2half_rn(v[i]);
    ((uint4*)H)[t] = Hh.q;
}

__global__ void convert_W_kernel(const float* __restrict__ W,
                                 __half* __restrict__ H, int Nout) {
    __shared__ float tile[32][33];
    const int tx = threadIdx.x & 31, ty = threadIdx.x >> 5;
    const int n0 = blockIdx.x * 32, k0 = blockIdx.y * 32;
#pragma unroll
    for (int i = 0; i < 4; i++) {
        int k = k0 + ty + i * 8;
        tile[ty + i * 8][tx] = W[(size_t)k * Nout + n0 + tx];
    }
    __syncthreads();
#pragma unroll
    for (int i = 0; i < 4; i++) {
        int n = n0 + ty + i * 8;
        H[(size_t)n * DIM + k0 + tx] = __float2half_rn(tile[tx][ty + i * 8]);
    }
}

// ---------------------------------------------------------------------------
// Fused middle stage, warp-per-token, MMA-based; qkv input is fp16.
// (unchanged from R14 winner)
// ---------------------------------------------------------------------------
__global__ __launch_bounds__(256)
void attn_kernel(const __half* __restrict__ qkv,
                 const float* __restrict__ fcos, const float* __restrict__ fsin,
                 const float* __restrict__ g_q, const float* __restrict__ g_k,
                 __half* __restrict__ ah) {
    __shared__ __align__(16) __half sQ[8][NHEAD * HDIM];   // 2KB per warp
    __shared__ __align__(16) __half sK[8][NHEAD * HDIM];
    __shared__ __align__(16) __half sV[8][NHEAD * HDIM];

    const int w = threadIdx.x >> 5;
    const int lane = threadIdx.x & 31;
    const int token = blockIdx.x * 8 + w;
    const int n_idx = token & (SEQ - 1);
    const __half* base = qkv + (size_t)token * QKVDIM;

    const uint32_t qb = s2u(&sQ[w][0]);
    const uint32_t kb = s2u(&sK[w][0]);
    const uint32_t vb = s2u(&sV[w][0]);

    // ---- Phase 1a: q (lanes 0-15) / k (lanes 16-31): one head per lane ----
    {
        const int hh = lane & 15;
        const __half* src = base + (lane < 16 ? 0 : DIM) + hh * HDIM;
        uint4 raw[8];
#pragma unroll
        for (int i = 0; i < 8; i++) raw[i] = ((const uint4*)src)[i];
        float vr[64];
#pragma unroll
        for (int i = 0; i < 8; i++) {
            const __half2* h2 = (const __half2*)&raw[i];
#pragma unroll
            for (int j = 0; j < 4; j++) {
                float2 f = __half22float2(h2[j]);
                vr[i * 8 + j * 2]     = f.x;
                vr[i * 8 + j * 2 + 1] = f.y;
            }
        }
        float ssum = 0.f;
#pragma unroll
        for (int e = 0; e < 64; e++) ssum += vr[e] * vr[e];
        float inv = 1.f / (sqrtf(ssum) * 0.125f + 1e-6f);   // ||x||*d^-0.5, d=64
        const float* gg = (lane < 16) ? g_q : g_k;

        union { __half2 h[4]; uint4 u; } pk[8];
#pragma unroll
        for (int p = 0; p < 32; p++) {
            float cc = fcos[n_idx * 32 + p];
            float sn = fsin[n_idx * 32 + p];
            float re = vr[2 * p] * inv * gg[2 * p];
            float im = vr[2 * p + 1] * inv * gg[2 * p + 1];
            pk[p >> 2].h[p & 3] = __floats2half2_rn(re * cc - im * sn,
                                                    re * sn + im * cc);
        }
        char* dst = (char*)((lane < 16) ? &sQ[w][0] : &sK[w][0]);
#pragma unroll
        for (int u = 0; u < 8; u++)
            *(uint4*)(dst + sw_off(hh, u)) = pk[u].u;
    }
    // ---- Phase 1b: v -> swizzled smem (fp16 passthrough, no conversion) ----
    {
        const int row = lane >> 1, ub = (lane & 1) * 4;
        const __half* vsrc = base + 2 * DIM + row * HDIM + (lane & 1) * 32;
        char* dst = (char*)&sV[w][0];
#pragma unroll
        for (int u2 = 0; u2 < 4; u2++) {
            uint4 d = ((const uint4*)vsrc)[u2];
            *(uint4*)(dst + sw_off(row, ub + u2)) = d;
        }
    }
    __syncwarp();

    // ---- Phase 2: S = Q K^T (m16n16k64 => 2 n-tiles x 4 k16) ----
    float accS[2][4] = {{0.f,0.f,0.f,0.f},{0.f,0.f,0.f,0.f}};
#pragma unroll
    for (int kk = 0; kk < 4; kk++) {
        uint32_t a[4];
        {
            const int row = lane & 15;
            const int au = kk * 2 + (lane >> 4);
            ldsm_x4(a[0], a[1], a[2], a[3], qb + sw_off(row, au));
        }
        uint32_t b[4];
        {
            const int row = ((lane >> 4) & 1) * 8 + (lane & 7);
            const int bu = kk * 2 + ((lane >> 3) & 1);
            ldsm_x4(b[0], b[1], b[2], b[3], kb + sw_off(row, bu));
        }
        mma16816(accS[0], a, b);
        mma16816(accS[1], a, b + 2);
    }

    // ---- Phase 3: softmax over 16 cols (rows r=lane/4 and r+8) ----
    float m0 = fmaxf(fmaxf(accS[0][0], accS[0][1]), fmaxf(accS[1][0], accS[1][1]));
    float m1 = fmaxf(fmaxf(accS[0][2], accS[0][3]), fmaxf(accS[1][2], accS[1][3]));
    m0 = fmaxf(m0, __shfl_xor_sync(0xffffffffu, m0, 1));
    m0 = fmaxf(m0, __shfl_xor_sync(0xffffffffu, m0, 2));
    m1 = fmaxf(m1, __shfl_xor_sync(0xffffffffu, m1, 1));
    m1 = fmaxf(m1, __shfl_xor_sync(0xffffffffu, m1, 2));
    float e00 = __expf(0.125f * (accS[0][0] - m0));
    float e01 = __expf(0.125f * (accS[0][1] - m0));
    float e10 = __expf(0.125f * (accS[1][0] - m0));
    float e11 = __expf(0.125f * (accS[1][1] - m0));
    float f00 = __expf(0.125f * (accS[0][2] - m1));
    float f01 = __expf(0.125f * (accS[0][3] - m1));
    float f10 = __expf(0.125f * (accS[1][2] - m1));
    float f11 = __expf(0.125f * (accS[1][3] - m1));
    float s0 = e00 + e01 + e10 + e11;
    float s1 = f00 + f01 + f10 + f11;
    s0 += __shfl_xor_sync(0xffffffffu, s0, 1);
    s0 += __shfl_xor_sync(0xffffffffu, s0, 2);
    s1 += __shfl_xor_sync(0xffffffffu, s1, 1);
    s1 += __shfl_xor_sync(0xffffffffu, s1, 2);
    float r0i = 1.f / s0, r1i = 1.f / s1;

    // ---- Phase 4: P fragments ----
    uint32_t aP[4];
    {
        __half2 h;
        h = __floats2half2_rn(e00 * r0i, e01 * r0i); aP[0] = *(uint32_t*)&h;
        h = __floats2half2_rn(f00 * r1i, f01 * r1i); aP[1] = *(uint32_t*)&h;
        h = __floats2half2_rn(e10 * r0i, e11 * r0i); aP[2] = *(uint32_t*)&h;
        h = __floats2half2_rn(f10 * r1i, f11 * r1i); aP[3] = *(uint32_t*)&h;
    }

    // ---- Phase 5: O = P @ V (m16n64k16 => 8 n-tiles, trans-ldmatrix V) ----
    float accO[8][4];
#pragma unroll
    for (int t = 0; t < 8; t++)
#pragma unroll
        for (int e = 0; e < 4; e++) accO[t][e] = 0.f;
#pragma unroll
    for (int dt2 = 0; dt2 < 4; dt2++) {
        uint32_t b[4];
        const int grp = lane >> 3;
        const int krow = (grp & 1) * 8 + (lane & 7);
        const int dt = dt2 * 2 + (grp >> 1);
        ldsm_x4_t(b[0], b[1], b[2], b[3], vb + sw_off(krow, dt));
        mma16816(accO[2 * dt2], aP, b);
        mma16816(accO[2 * dt2 + 1], aP, b + 2);
    }

    // ---- Phase 6: write O to ah (fp16, row = head, col = d) ----
    {
        __half* orow = ah + (size_t)token * DIM;
        const int rr = lane >> 2, cc0 = 2 * (lane & 3);
#pragma unroll
        for (int t = 0; t < 8; t++) {
            *(__half2*)(orow + rr * HDIM + t * 8 + cc0) =
                __floats2half2_rn(accO[t][0], accO[t][1]);
            *(__half2*)(orow + (rr + 8) * HDIM + t * 8 + cc0) =
                __floats2half2_rn(accO[t][2], accO[t][3]);
        }
    }
}

// ---------------------------------------------------------------------------
extern "C" void kernel_launch(void* const* d_in, const int* in_sizes, int n_in,
                              void* d_out, int out_size) {
    const float* x     = (const float*)d_in[0];
    const float* fcos  = (const float*)d_in[1];
    const float* fsin  = (const float*)d_in[2];
    const float* wqkv  = (const float*)d_in[3];
    const float* gq    = (const float*)d_in[4];
    const float* gk    = (const float*)d_in[5];
    const float* wproj = (const float*)d_in[6];
    const float* bproj = (const float*)d_in[7];
    float* out = (float*)d_out;

    void *p_xh, *p_wqh, *p_wph, *p_ah, *p_qkv;
    cudaGetSymbolAddress(&p_xh,  g_xh);
    cudaGetSymbolAddress(&p_wqh, g_wqh);
    cudaGetSymbolAddress(&p_wph, g_wph);
    cudaGetSymbolAddress(&p_ah,  g_ah);
    cudaGetSymbolAddress(&p_qkv, g_qkv);

    cudaFuncSetAttribute((const void*)&mma_gemm<false, true>,
                         cudaFuncAttributeMaxDynamicSharedMemorySize, GEMM_SMEM_TOTAL);
    cudaFuncSetAttribute((const void*)&mma_gemm<true, false>,
                         cudaFuncAttributeMaxDynamicSharedMemorySize, GEMM_SMEM_TOTAL);

    {
        size_t total8 = (size_t)TOKENS * DIM / 8;
        convert_A_kernel<<<(unsigned)((total8 + 255) / 256), 256>>>(
            x, (__half*)p_xh, total8);
    }
    convert_W_kernel<<<dim3(QKVDIM / 32, DIM / 32), 256>>>(
        wqkv, (__half*)p_wqh, QKVDIM);
    convert_W_kernel<<<dim3(DIM / 32, DIM / 32), 256>>>(
        wproj, (__half*)p_wph, DIM);

    // qkv = x @ w_qkv  (single-pass fp16 MMA, fp32 accum, fp16 output)
    mma_gemm<false, true><<<dim3(QKVDIM / BN, TOKENS / BM), 256, GEMM_SMEM_TOTAL>>>(
        (const __half*)p_xh, (const __half*)p_wqh, nullptr, p_qkv, QKVDIM);

    // fused RMSNorm+RoPE+head-mixing attention (MMA) -> ah fp16
    attn_kernel<<<TOKENS / 8, 256>>>((const __half*)p_qkv, fcos, fsin, gq, gk,
                                     (__half*)p_ah);

    // out = att @ w_proj + b  (fp32 output)
    mma_gemm<true, false><<<dim3(DIM / BN, TOKENS / BM), 256, GEMM_SMEM_TOTAL>>>(
        (const __half*)p_ah, (const __half*)p_wph, bproj, out, DIM);
}